// round 1
// baseline (speedup 1.0000x reference)
#include <cuda_runtime.h>
#include <cuda_bf16.h>
#include <math.h>

// Problem constants
#define BATCH 4
#define SEQ   2048
#define DMODEL 512
#define NHEADS 8
#define NKVHEADS 4
#define HDIM  64
#define GROUP (NHEADS / NKVHEADS)   // 2
#define ROWS  (BATCH * SEQ)         // 8192
#define KVDIM (NKVHEADS * HDIM)     // 256

// -------- device scratch (no allocations allowed) --------
__device__ float g_q[ROWS * DMODEL];   // 16 MB
__device__ float g_k[ROWS * KVDIM];    //  8 MB
__device__ float g_v[ROWS * KVDIM];    //  8 MB
__device__ float g_y[ROWS * DMODEL];   // 16 MB

// ============================================================
// GEMM: C[M,N] = A[M,K] * B[N,K]^T   (both row-major, NT form)
// 128x128 tile, BK=16, 256 threads, 8x8 per thread. FMA-bound.
// ============================================================
#define BM 128
#define BN 128
#define BKT 16

__global__ __launch_bounds__(256)
void gemm_nt(const float* __restrict__ A, const float* __restrict__ Bw,
             float* __restrict__ C, int M, int N, int K) {
    __shared__ float As[BM][BKT + 1];
    __shared__ float Bs[BN][BKT + 1];

    const int tid = threadIdx.x;
    const int tx = tid & 15;        // 0..15
    const int ty = tid >> 4;        // 0..15
    const int row0 = ty * 8;
    const int col0 = tx * 8;
    const int bm = blockIdx.y * BM;
    const int bn = blockIdx.x * BN;

    const int lk = tid & 15;        // k within tile (coalesced gmem reads)
    const int lm = tid >> 4;        // base row

    float acc[8][8];
#pragma unroll
    for (int i = 0; i < 8; i++)
#pragma unroll
        for (int j = 0; j < 8; j++) acc[i][j] = 0.f;

    for (int k0 = 0; k0 < K; k0 += BKT) {
#pragma unroll
        for (int i = 0; i < 8; i++) {
            As[lm + 16 * i][lk] = A[(size_t)(bm + lm + 16 * i) * K + k0 + lk];
            Bs[lm + 16 * i][lk] = Bw[(size_t)(bn + lm + 16 * i) * K + k0 + lk];
        }
        __syncthreads();
#pragma unroll
        for (int kk = 0; kk < BKT; kk++) {
            float a[8], b[8];
#pragma unroll
            for (int i = 0; i < 8; i++) a[i] = As[row0 + i][kk];
#pragma unroll
            for (int j = 0; j < 8; j++) b[j] = Bs[col0 + j][kk];
#pragma unroll
            for (int i = 0; i < 8; i++)
#pragma unroll
                for (int j = 0; j < 8; j++)
                    acc[i][j] = fmaf(a[i], b[j], acc[i][j]);
        }
        __syncthreads();
    }

#pragma unroll
    for (int i = 0; i < 8; i++) {
        float* crow = C + (size_t)(bm + row0 + i) * N + bn + col0;
#pragma unroll
        for (int j = 0; j < 8; j++) crow[j] = acc[i][j];
    }
}

// ============================================================
// RMSNorm (per 64-dim head) + partial RoPE(16 dims) + optional
// per-head gain. One warp per (b, t, head). data: [B*T, heads, 64]
// ============================================================
__global__ void norm_rope_kernel(float* __restrict__ data,
                                 const float* __restrict__ gain,
                                 int heads, int apply_gain) {
    const int w = (blockIdx.x * blockDim.x + threadIdx.x) >> 5;
    const int lane = threadIdx.x & 31;
    const int total = ROWS * heads;
    if (w >= total) return;

    const int h = w % heads;
    const int t = (w / heads) % SEQ;

    float* p = data + (size_t)w * HDIM;
    float v0 = p[lane];
    float v1 = p[lane + 32];

    float ss = v0 * v0 + v1 * v1;
#pragma unroll
    for (int o = 16; o > 0; o >>= 1) ss += __shfl_xor_sync(0xFFFFFFFFu, ss, o);

    const float r = rsqrtf(ss * (1.0f / 64.0f) + 1.1920929e-07f);
    v0 *= r;
    v1 *= r;

    // RoPE over first 16 dims: half=8; x1=d[0:8], x2=d[8:16]
    const float other = __shfl_xor_sync(0xFFFFFFFFu, v0, 8);
    if (lane < 16) {
        const int i = lane & 7;
        const float inv_freq = __powf(10000.0f, -(float)i * 0.125f);
        const float ang = (float)t * inv_freq;
        float c, s;
        __sincosf(ang, &s, &c);
        const float x1 = (lane < 8) ? v0 : other;
        const float x2 = (lane < 8) ? other : v0;
        v0 = (lane < 8) ? fmaf(x1, c, x2 * s) : fmaf(-x1, s, x2 * c);
    }

    if (apply_gain) {
        const float g = gain[h];
        v0 *= g;
        v1 *= g;
    }
    p[lane] = v0;
    p[lane + 32] = v1;
}

// ============================================================
// Causal flash attention, fp32.
// Grid: (T/64, NHEADS, BATCH). Block: 64 threads (thread = 1 q row).
// smem: K tile 16KB + V tile 16KB + S tile 16KB = 48KB exactly.
// q row and 64-dim accumulator held in registers.
// ============================================================
__global__ __launch_bounds__(64)
void attn_kernel(const float* __restrict__ q, const float* __restrict__ k,
                 const float* __restrict__ v, float* __restrict__ o) {
    __shared__ float ks[64 * 64];
    __shared__ float vs[64 * 64];
    __shared__ float ssm[64 * 64];   // ssm[j*64 + tid] : conflict-free

    const int tid = threadIdx.x;     // 0..63 : q row within tile
    const int qb = blockIdx.x;
    const int h = blockIdx.y;
    const int b = blockIdx.z;
    const int kvh = h / GROUP;
    const int r = qb * 64 + tid;     // global q position in sequence

    const float* qrow = q + ((size_t)(b * SEQ + r) * NHEADS + h) * HDIM;
    float qreg[64], acc[64];
#pragma unroll
    for (int c = 0; c < 16; c++) {
        float4 t4 = ((const float4*)qrow)[c];
        qreg[4 * c + 0] = t4.x * 0.125f;   // 1/sqrt(64) folded into q
        qreg[4 * c + 1] = t4.y * 0.125f;
        qreg[4 * c + 2] = t4.z * 0.125f;
        qreg[4 * c + 3] = t4.w * 0.125f;
    }
#pragma unroll
    for (int d = 0; d < 64; d++) acc[d] = 0.f;

    float m = -1e30f, l = 0.f;

    const float* kbh = k + ((size_t)b * SEQ * NKVHEADS + kvh) * HDIM;
    const float* vbh = v + ((size_t)b * SEQ * NKVHEADS + kvh) * HDIM;

    for (int kt = 0; kt <= qb; kt++) {
        // cooperative load of 64x64 K and V tiles (coalesced float4)
        const float* kbase = kbh + (size_t)kt * 64 * KVDIM;
        const float* vbase = vbh + (size_t)kt * 64 * KVDIM;
#pragma unroll
        for (int i = 0; i < 16; i++) {
            const int idx = i * 64 + tid;
            const int row = idx >> 4;
            const int c4 = idx & 15;
            ((float4*)ks)[row * 16 + c4] =
                ((const float4*)(kbase + (size_t)row * KVDIM))[c4];
            ((float4*)vs)[row * 16 + c4] =
                ((const float4*)(vbase + (size_t)row * KVDIM))[c4];
        }
        __syncthreads();

        const int jlim = (kt == qb) ? (tid + 1) : 64;   // causal
        float tm = -1e30f;
        for (int j = 0; j < jlim; j++) {
            float s = 0.f;
#pragma unroll
            for (int c = 0; c < 16; c++) {
                float4 k4 = ((const float4*)ks)[j * 16 + c];
                s = fmaf(qreg[4 * c + 0], k4.x, s);
                s = fmaf(qreg[4 * c + 1], k4.y, s);
                s = fmaf(qreg[4 * c + 2], k4.z, s);
                s = fmaf(qreg[4 * c + 3], k4.w, s);
            }
            ssm[j * 64 + tid] = s;
            tm = fmaxf(tm, s);
        }

        const float mn = fmaxf(m, tm);
        const float corr = __expf(m - mn);
        l *= corr;
#pragma unroll
        for (int d = 0; d < 64; d++) acc[d] *= corr;

        for (int j = 0; j < jlim; j++) {
            const float p = __expf(ssm[j * 64 + tid] - mn);
            l += p;
#pragma unroll
            for (int c = 0; c < 16; c++) {
                float4 v4 = ((const float4*)vs)[j * 16 + c];
                acc[4 * c + 0] = fmaf(p, v4.x, acc[4 * c + 0]);
                acc[4 * c + 1] = fmaf(p, v4.y, acc[4 * c + 1]);
                acc[4 * c + 2] = fmaf(p, v4.z, acc[4 * c + 2]);
                acc[4 * c + 3] = fmaf(p, v4.w, acc[4 * c + 3]);
            }
        }
        m = mn;
        __syncthreads();
    }

    const float inv = 1.0f / l;
    float* orow = o + ((size_t)(b * SEQ + r) * NHEADS + h) * HDIM;
#pragma unroll
    for (int c = 0; c < 16; c++) {
        float4 t4;
        t4.x = acc[4 * c + 0] * inv;
        t4.y = acc[4 * c + 1] * inv;
        t4.z = acc[4 * c + 2] * inv;
        t4.w = acc[4 * c + 3] * inv;
        ((float4*)orow)[c] = t4;
    }
}

// ============================================================
// Launch
// ============================================================
extern "C" void kernel_launch(void* const* d_in, const int* in_sizes, int n_in,
                              void* d_out, int out_size) {
    const float* x      = (const float*)d_in[0];
    const float* w_q    = (const float*)d_in[1];
    const float* w_k    = (const float*)d_in[2];
    const float* w_v    = (const float*)d_in[3];
    const float* w_proj = (const float*)d_in[4];
    const float* q_gain = (const float*)d_in[5];
    float* out = (float*)d_out;

    float *qbuf, *kbuf, *vbuf, *ybuf;
    cudaGetSymbolAddress((void**)&qbuf, g_q);
    cudaGetSymbolAddress((void**)&kbuf, g_k);
    cudaGetSymbolAddress((void**)&vbuf, g_v);
    cudaGetSymbolAddress((void**)&ybuf, g_y);

    // QKV projections
    gemm_nt<<<dim3(DMODEL / BN, ROWS / BM), 256>>>(x, w_q, qbuf, ROWS, DMODEL, DMODEL);
    gemm_nt<<<dim3(KVDIM / BN, ROWS / BM), 256>>>(x, w_k, kbuf, ROWS, KVDIM, DMODEL);
    gemm_nt<<<dim3(KVDIM / BN, ROWS / BM), 256>>>(x, w_v, vbuf, ROWS, KVDIM, DMODEL);

    // RMSNorm + RoPE (+gain for q)
    {
        const int qwarps = ROWS * NHEADS;            // 65536 warps
        norm_rope_kernel<<<(qwarps * 32) / 256, 256>>>(qbuf, q_gain, NHEADS, 1);
        const int kwarps = ROWS * NKVHEADS;          // 32768 warps
        norm_rope_kernel<<<(kwarps * 32) / 256, 256>>>(kbuf, nullptr, NKVHEADS, 0);
    }

    // Causal flash attention
    attn_kernel<<<dim3(SEQ / 64, NHEADS, BATCH), 64>>>(qbuf, kbuf, vbuf, ybuf);

    // Output projection
    gemm_nt<<<dim3(DMODEL / BN, ROWS / BM), 256>>>(ybuf, w_proj, out, ROWS, DMODEL, DMODEL);
}

// round 3
// speedup vs baseline: 1.1688x; 1.1688x over previous
#include <cuda_runtime.h>
#include <cuda_bf16.h>
#include <math.h>

// Problem constants
#define BATCH 4
#define SEQ   2048
#define DMODEL 512
#define NHEADS 8
#define NKVHEADS 4
#define HDIM  64
#define GROUP (NHEADS / NKVHEADS)   // 2
#define ROWS  (BATCH * SEQ)         // 8192
#define KVDIM (NKVHEADS * HDIM)     // 256

// -------- device scratch (no allocations allowed) --------
__device__ float g_q[ROWS * DMODEL];   // 16 MB
__device__ float g_k[ROWS * KVDIM];    //  8 MB
__device__ float g_v[ROWS * KVDIM];    //  8 MB
__device__ float g_y[ROWS * DMODEL];   // 16 MB

// ============================================================
// GEMM core: C[M,N] = A[M,K] * B[N,K]^T  (row-major, NT form)
// 128x128 tile, BK=16, 256 threads, 8x8 per thread.
// Smem k-major (+4 pad) -> vectorized LDS.128 in the mainloop.
// Register prefetch of the next k-tile overlaps LDG with FFMA.
// ============================================================
#define BM 128
#define BN 128
#define BKT 16
#define SPAD 4

__device__ __forceinline__
void gemm_tile(const float* __restrict__ A, const float* __restrict__ Bw,
               float* __restrict__ C, int N, int K, int bm, int bn) {
    __shared__ float As[BKT][BM + SPAD];   // k-major
    __shared__ float Bs[BKT][BN + SPAD];

    const int tid = threadIdx.x;
    const int tx = tid & 15;        // 0..15
    const int ty = tid >> 4;        // 0..15
    const int row0 = ty * 8;
    const int col0 = tx * 8;

    // global-load mapping: 512 float4 per 128x16 tile, 2 per thread
    const int r0 = tid >> 2;             // row for u=0 (0..63)
    const int c0 = tid & 3;              // float4 col (0..3)
    const int r1 = (tid + 256) >> 2;     // row for u=1 (64..127)

    float acc[8][8];
#pragma unroll
    for (int i = 0; i < 8; i++)
#pragma unroll
        for (int j = 0; j < 8; j++) acc[i][j] = 0.f;

    float4 ra[2], rb[2];
    ra[0] = *(const float4*)(A  + (size_t)(bm + r0) * K + c0 * 4);
    ra[1] = *(const float4*)(A  + (size_t)(bm + r1) * K + c0 * 4);
    rb[0] = *(const float4*)(Bw + (size_t)(bn + r0) * K + c0 * 4);
    rb[1] = *(const float4*)(Bw + (size_t)(bn + r1) * K + c0 * 4);

    for (int k0 = 0; k0 < K; k0 += BKT) {
        As[c0 * 4 + 0][r0] = ra[0].x; As[c0 * 4 + 1][r0] = ra[0].y;
        As[c0 * 4 + 2][r0] = ra[0].z; As[c0 * 4 + 3][r0] = ra[0].w;
        As[c0 * 4 + 0][r1] = ra[1].x; As[c0 * 4 + 1][r1] = ra[1].y;
        As[c0 * 4 + 2][r1] = ra[1].z; As[c0 * 4 + 3][r1] = ra[1].w;
        Bs[c0 * 4 + 0][r0] = rb[0].x; Bs[c0 * 4 + 1][r0] = rb[0].y;
        Bs[c0 * 4 + 2][r0] = rb[0].z; Bs[c0 * 4 + 3][r0] = rb[0].w;
        Bs[c0 * 4 + 0][r1] = rb[1].x; Bs[c0 * 4 + 1][r1] = rb[1].y;
        Bs[c0 * 4 + 2][r1] = rb[1].z; Bs[c0 * 4 + 3][r1] = rb[1].w;
        __syncthreads();

        const int kn = k0 + BKT;
        if (kn < K) {   // prefetch next tile (overlapped with compute below)
            ra[0] = *(const float4*)(A  + (size_t)(bm + r0) * K + kn + c0 * 4);
            ra[1] = *(const float4*)(A  + (size_t)(bm + r1) * K + kn + c0 * 4);
            rb[0] = *(const float4*)(Bw + (size_t)(bn + r0) * K + kn + c0 * 4);
            rb[1] = *(const float4*)(Bw + (size_t)(bn + r1) * K + kn + c0 * 4);
        }

#pragma unroll
        for (int kk = 0; kk < BKT; kk++) {
            float4 a01 = *(const float4*)&As[kk][row0];
            float4 a23 = *(const float4*)&As[kk][row0 + 4];
            float4 b01 = *(const float4*)&Bs[kk][col0];
            float4 b23 = *(const float4*)&Bs[kk][col0 + 4];
            float a[8] = {a01.x, a01.y, a01.z, a01.w, a23.x, a23.y, a23.z, a23.w};
            float b[8] = {b01.x, b01.y, b01.z, b01.w, b23.x, b23.y, b23.z, b23.w};
#pragma unroll
            for (int i = 0; i < 8; i++)
#pragma unroll
                for (int j = 0; j < 8; j++)
                    acc[i][j] = fmaf(a[i], b[j], acc[i][j]);
        }
        __syncthreads();
    }

#pragma unroll
    for (int i = 0; i < 8; i++) {
        float* crow = C + (size_t)(bm + row0 + i) * N + bn + col0;
        float4 lo = {acc[i][0], acc[i][1], acc[i][2], acc[i][3]};
        float4 hi = {acc[i][4], acc[i][5], acc[i][6], acc[i][7]};
        ((float4*)crow)[0] = lo;
        ((float4*)crow)[1] = hi;
    }
}

// Plain GEMM (used for output projection)
__global__ __launch_bounds__(256)
void gemm_nt(const float* __restrict__ A, const float* __restrict__ Bw,
             float* __restrict__ C, int N, int K) {
    gemm_tile(A, Bw, C, N, K, blockIdx.y * BM, blockIdx.x * BN);
}

// Fused QKV projection: one launch, 8 n-tiles x 64 m-tiles = 512 blocks.
// bx 0..3 -> Q cols, 4..5 -> K cols, 6..7 -> V cols.
__global__ __launch_bounds__(256)
void gemm_qkv(const float* __restrict__ x,
              const float* __restrict__ w_q, const float* __restrict__ w_k,
              const float* __restrict__ w_v,
              float* __restrict__ q, float* __restrict__ k,
              float* __restrict__ v) {
    const int bx = blockIdx.x;
    const int bm = blockIdx.y * BM;
    if (bx < 4) {
        gemm_tile(x, w_q, q, DMODEL, DMODEL, bm, bx * BN);
    } else if (bx < 6) {
        gemm_tile(x, w_k, k, KVDIM, DMODEL, bm, (bx - 4) * BN);
    } else {
        gemm_tile(x, w_v, v, KVDIM, DMODEL, bm, (bx - 6) * BN);
    }
}

// ============================================================
// RMSNorm (per 64-dim head) + partial RoPE(16 dims) + q-gain.
// One warp per (b, t, head). Handles q (first ROWS*NHEADS warps)
// and k (next ROWS*NKVHEADS warps) in a single launch.
// ============================================================
#define QWARPS (ROWS * NHEADS)      // 65536
#define KWARPS (ROWS * NKVHEADS)    // 32768

__global__ void norm_rope_kernel(float* __restrict__ qd, float* __restrict__ kd,
                                 const float* __restrict__ gain) {
    int w = (blockIdx.x * blockDim.x + threadIdx.x) >> 5;
    const int lane = threadIdx.x & 31;

    float* p;
    int t, h;
    bool is_q;
    if (w < QWARPS) {
        is_q = true;
        h = w % NHEADS;
        t = (w / NHEADS) % SEQ;
        p = qd + (size_t)w * HDIM;
    } else {
        w -= QWARPS;
        if (w >= KWARPS) return;
        is_q = false;
        h = 0;
        t = (w / NKVHEADS) % SEQ;
        p = kd + (size_t)w * HDIM;
    }

    float v0 = p[lane];
    float v1 = p[lane + 32];

    float ss = v0 * v0 + v1 * v1;
#pragma unroll
    for (int o = 16; o > 0; o >>= 1) ss += __shfl_xor_sync(0xFFFFFFFFu, ss, o);

    const float r = rsqrtf(ss * (1.0f / 64.0f) + 1.1920929e-07f);
    v0 *= r;
    v1 *= r;

    // RoPE over first 16 dims: half=8; x1=d[0:8], x2=d[8:16]
    const float other = __shfl_xor_sync(0xFFFFFFFFu, v0, 8);
    if (lane < 16) {
        const int i = lane & 7;
        const float inv_freq = __powf(10000.0f, -(float)i * 0.125f);
        const float ang = (float)t * inv_freq;
        float c, s;
        __sincosf(ang, &s, &c);
        const float x1 = (lane < 8) ? v0 : other;
        const float x2 = (lane < 8) ? other : v0;
        v0 = (lane < 8) ? fmaf(x1, c, x2 * s) : fmaf(-x1, s, x2 * c);
    }

    if (is_q) {
        const float g = gain[h];
        v0 *= g;
        v1 *= g;
    }
    p[lane] = v0;
    p[lane + 32] = v1;
}

// ============================================================
// Causal flash attention, fp32.
// Grid: (T/64, NHEADS, BATCH). Block: 64 threads (thread = 1 q row).
// smem: K 16KB + V 16KB + S 16KB = 48KB -> 4 blocks/SM.
// qk dot uses 4 partial accumulators (chain depth 16, not 64).
// Diagonal tile runs full 64 j with -inf masking so loops unroll.
// ============================================================
__global__ __launch_bounds__(64)
void attn_kernel(const float* __restrict__ q, const float* __restrict__ k,
                 const float* __restrict__ v, float* __restrict__ o) {
    __shared__ float ks[64 * 64];
    __shared__ float vs[64 * 64];
    __shared__ float ssm[64 * 64];   // ssm[j*64 + tid] : conflict-free

    const int tid = threadIdx.x;     // 0..63 : q row within tile
    const int qb = blockIdx.x;
    const int h = blockIdx.y;
    const int b = blockIdx.z;
    const int kvh = h / GROUP;

    const float* qrow = q + ((size_t)(b * SEQ + qb * 64 + tid) * NHEADS + h) * HDIM;
    float qreg[64], acc[64];
#pragma unroll
    for (int c = 0; c < 16; c++) {
        float4 t4 = ((const float4*)qrow)[c];
        qreg[4 * c + 0] = t4.x * 0.125f;   // 1/sqrt(64) folded into q
        qreg[4 * c + 1] = t4.y * 0.125f;
        qreg[4 * c + 2] = t4.z * 0.125f;
        qreg[4 * c + 3] = t4.w * 0.125f;
    }
#pragma unroll
    for (int d = 0; d < 64; d++) acc[d] = 0.f;

    float m = -1e30f, l = 0.f;

    const float* kbh = k + ((size_t)b * SEQ * NKVHEADS + kvh) * HDIM;
    const float* vbh = v + ((size_t)b * SEQ * NKVHEADS + kvh) * HDIM;

    for (int kt = 0; kt <= qb; kt++) {
        // cooperative load of 64x64 K and V tiles (coalesced float4)
        const float* kbase = kbh + (size_t)kt * 64 * KVDIM;
        const float* vbase = vbh + (size_t)kt * 64 * KVDIM;
#pragma unroll
        for (int i = 0; i < 16; i++) {
            const int idx = i * 64 + tid;
            const int row = idx >> 4;
            const int c4 = idx & 15;
            ((float4*)ks)[row * 16 + c4] =
                ((const float4*)(kbase + (size_t)row * KVDIM))[c4];
            ((float4*)vs)[row * 16 + c4] =
                ((const float4*)(vbase + (size_t)row * KVDIM))[c4];
        }
        __syncthreads();

        const bool diag = (kt == qb);
        float tm = -1e30f;
#pragma unroll 2
        for (int j = 0; j < 64; j++) {
            float s0 = 0.f, s1 = 0.f, s2 = 0.f, s3 = 0.f;
#pragma unroll
            for (int c = 0; c < 16; c += 4) {
                float4 k0 = ((const float4*)ks)[j * 16 + c + 0];
                float4 k1 = ((const float4*)ks)[j * 16 + c + 1];
                float4 k2 = ((const float4*)ks)[j * 16 + c + 2];
                float4 k3 = ((const float4*)ks)[j * 16 + c + 3];
                s0 = fmaf(qreg[4*c + 0],  k0.x, s0);
                s0 = fmaf(qreg[4*c + 1],  k0.y, s0);
                s0 = fmaf(qreg[4*c + 2],  k0.z, s0);
                s0 = fmaf(qreg[4*c + 3],  k0.w, s0);
                s1 = fmaf(qreg[4*c + 4],  k1.x, s1);
                s1 = fmaf(qreg[4*c + 5],  k1.y, s1);
                s1 = fmaf(qreg[4*c + 6],  k1.z, s1);
                s1 = fmaf(qreg[4*c + 7],  k1.w, s1);
                s2 = fmaf(qreg[4*c + 8],  k2.x, s2);
                s2 = fmaf(qreg[4*c + 9],  k2.y, s2);
                s2 = fmaf(qreg[4*c + 10], k2.z, s2);
                s2 = fmaf(qreg[4*c + 11], k2.w, s2);
                s3 = fmaf(qreg[4*c + 12], k3.x, s3);
                s3 = fmaf(qreg[4*c + 13], k3.y, s3);
                s3 = fmaf(qreg[4*c + 14], k3.z, s3);
                s3 = fmaf(qreg[4*c + 15], k3.w, s3);
            }
            float s = (s0 + s1) + (s2 + s3);
            if (diag && j > tid) s = -1e30f;   // causal mask on diagonal tile
            ssm[j * 64 + tid] = s;
            tm = fmaxf(tm, s);
        }

        const float mn = fmaxf(m, tm);
        const float corr = __expf(m - mn);
        l *= corr;
#pragma unroll
        for (int d = 0; d < 64; d++) acc[d] *= corr;

#pragma unroll 2
        for (int j = 0; j < 64; j++) {
            const float p = __expf(ssm[j * 64 + tid] - mn);   // masked -> 0
            l += p;
#pragma unroll
            for (int c = 0; c < 16; c++) {
                float4 v4 = ((const float4*)vs)[j * 16 + c];
                acc[4 * c + 0] = fmaf(p, v4.x, acc[4 * c + 0]);
                acc[4 * c + 1] = fmaf(p, v4.y, acc[4 * c + 1]);
                acc[4 * c + 2] = fmaf(p, v4.z, acc[4 * c + 2]);
                acc[4 * c + 3] = fmaf(p, v4.w, acc[4 * c + 3]);
            }
        }
        m = mn;
        __syncthreads();
    }

    const float inv = 1.0f / l;
    float* orow = o + ((size_t)(b * SEQ + qb * 64 + tid) * NHEADS + h) * HDIM;
#pragma unroll
    for (int c = 0; c < 16; c++) {
        float4 t4;
        t4.x = acc[4 * c + 0] * inv;
        t4.y = acc[4 * c + 1] * inv;
        t4.z = acc[4 * c + 2] * inv;
        t4.w = acc[4 * c + 3] * inv;
        ((float4*)orow)[c] = t4;
    }
}

// ============================================================
// Launch
// ============================================================
extern "C" void kernel_launch(void* const* d_in, const int* in_sizes, int n_in,
                              void* d_out, int out_size) {
    const float* x      = (const float*)d_in[0];
    const float* w_q    = (const float*)d_in[1];
    const float* w_k    = (const float*)d_in[2];
    const float* w_v    = (const float*)d_in[3];
    const float* w_proj = (const float*)d_in[4];
    const float* q_gain = (const float*)d_in[5];
    float* out = (float*)d_out;

    float *qbuf, *kbuf, *vbuf, *ybuf;
    cudaGetSymbolAddress((void**)&qbuf, g_q);
    cudaGetSymbolAddress((void**)&kbuf, g_k);
    cudaGetSymbolAddress((void**)&vbuf, g_v);
    cudaGetSymbolAddress((void**)&ybuf, g_y);

    // Fused QKV projection: 8 n-tiles (4 q, 2 k, 2 v) x 64 m-tiles
    gemm_qkv<<<dim3(8, ROWS / BM), 256>>>(x, w_q, w_k, w_v, qbuf, kbuf, vbuf);

    // Fused RMSNorm + RoPE (+gain for q) for q and k
    {
        const int warps = QWARPS + KWARPS;           // 98304
        norm_rope_kernel<<<(warps * 32) / 256, 256>>>(qbuf, kbuf, q_gain);
    }

    // Causal flash attention
    attn_kernel<<<dim3(SEQ / 64, NHEADS, BATCH), 64>>>(qbuf, kbuf, vbuf, ybuf);

    // Output projection
    gemm_nt<<<dim3(DMODEL / BN, ROWS / BM), 256>>>(ybuf, w_proj, out, DMODEL, DMODEL);
}